// round 12
// baseline (speedup 1.0000x reference)
#include <cuda_runtime.h>
#include <cuda_fp16.h>
#include <math.h>
#include <float.h>
#include <stdint.h>

// Problem constants
#define BB 2
#define TT 512
#define DM 3584
#define NQ 28
#define NKV 4
#define GRP 7
#define HH 128
#define SCACHE 3584
#define SEQ 4096

#define OUT_ELEMS (BB*TT*DM)
#define KV_ELEMS  (BB*SEQ*NKV*HH)

// Scratch
__device__ float  g_q  [BB*TT*NQ*HH];     // q proj fp32 (pre-rope)
__device__ __half g_qh [BB*TT*NQ*HH];     // q roped+scaled fp16
__device__ __half g_kh [KV_ELEMS];        // k cache fp16 (roped)
__device__ __half g_vh [KV_ELEMS];        // v cache fp16
__device__ __half g_ench[BB*TT*NQ*HH];    // attention output fp16
__device__ __half g_xh [BB*TT*DM];        // x fp16
__device__ __half g_wh [36*DM*HH];        // wq|wk|wv fp16
__device__ __half g_woh[DM*DM];           // wo fp16

__device__ __forceinline__ void mma_f16(float c[4], const uint32_t a[4], const uint32_t b[2]) {
    asm volatile("mma.sync.aligned.m16n8k16.row.col.f32.f16.f16.f32 "
        "{%0,%1,%2,%3}, {%4,%5,%6,%7}, {%8,%9}, {%0,%1,%2,%3};"
        : "+f"(c[0]), "+f"(c[1]), "+f"(c[2]), "+f"(c[3])
        : "r"(a[0]), "r"(a[1]), "r"(a[2]), "r"(a[3]), "r"(b[0]), "r"(b[1]));
}
__device__ __forceinline__ void ldsm4(uint32_t& r0, uint32_t& r1, uint32_t& r2, uint32_t& r3,
                                      uint32_t addr) {
    asm volatile("ldmatrix.sync.aligned.m8n8.x4.shared.b16 {%0,%1,%2,%3}, [%4];"
        : "=r"(r0), "=r"(r1), "=r"(r2), "=r"(r3) : "r"(addr));
}
__device__ __forceinline__ void ldsm4t(uint32_t& r0, uint32_t& r1, uint32_t& r2, uint32_t& r3,
                                       uint32_t addr) {
    asm volatile("ldmatrix.sync.aligned.m8n8.x4.trans.shared.b16 {%0,%1,%2,%3}, [%4];"
        : "=r"(r0), "=r"(r1), "=r"(r2), "=r"(r3) : "r"(addr));
}
__device__ __forceinline__ uint32_t smem_u32(const void* p) {
    uint32_t a;
    asm("{ .reg .u64 t; cvta.to.shared.u64 t, %1; cvt.u32.u64 %0, t; }" : "=r"(a) : "l"(p));
    return a;
}
__device__ __forceinline__ uint32_t pack_h2(float a, float b) {
    __half2 h = __floats2half2_rn(a, b);
    return *(uint32_t*)&h;
}
#define CP16(dst, src) \
    asm volatile("cp.async.cg.shared.global [%0], [%1], 16;" :: "r"(dst), "l"(src))
#define CP_COMMIT() asm volatile("cp.async.commit_group;" ::: "memory")
#define CP_WAIT1()  asm volatile("cp.async.wait_group 1;" ::: "memory")
#define CP_WAIT0()  asm volatile("cp.async.wait_group 0;" ::: "memory")

// ---------------------------------------------------------------------------
// fp32 -> fp16 converter (grid-stride, float4 -> 4 halves)
// ---------------------------------------------------------------------------
__global__ void conv_kernel(const float4* __restrict__ src, uint2* __restrict__ dst, int n4)
{
    for (int i = blockIdx.x*blockDim.x + threadIdx.x; i < n4; i += gridDim.x*blockDim.x) {
        float4 v = src[i];
        uint2 o;
        o.x = pack_h2(v.x, v.y);
        o.y = pack_h2(v.z, v.w);
        dst[i] = o;
    }
}

// ---------------------------------------------------------------------------
// Cache copy: fp32 outputs + fp16 mirrors (rows < SCACHE)
// ---------------------------------------------------------------------------
__global__ void cache_copy_kernel(const float4* __restrict__ ck,
                                  const float4* __restrict__ cv,
                                  float4* __restrict__ outk,
                                  float4* __restrict__ outv,
                                  uint2* __restrict__ kh,
                                  uint2* __restrict__ vh)
{
    const int per_b = SCACHE*NKV*HH/4;
    const int n4 = BB * per_b;
    for (int idx = blockIdx.x*blockDim.x + threadIdx.x; idx < n4;
         idx += gridDim.x*blockDim.x) {
        int b = idx / per_b;
        int r = idx - b*per_b;
        size_t o = (size_t)b*(SEQ*NKV*HH/4) + r;
        float4 a = ck[idx];
        float4 c = cv[idx];
        outk[o] = a;
        outv[o] = c;
        uint2 ka, vb;
        ka.x = pack_h2(a.x, a.y); ka.y = pack_h2(a.z, a.w);
        vb.x = pack_h2(c.x, c.y); vb.y = pack_h2(c.z, c.w);
        kh[o] = ka;
        vh[o] = vb;
    }
}

// ===========================================================================
// Dense GEMM — fp16 inputs, cp.async double-buffered, BK=64.
// A row-major [128 x K] fp16 (lda halves); B row-major [K x 128] fp16 (ldb),
// staged [k][n], fragments via ldmatrix.trans. 256 threads, 8 warps, 32x64.
// ===========================================================================
#define GBK   64
#define GCH   (DM/GBK)    // 56
#define ASTR  72          // A smem stride (halves): 144B rows
#define BSTR  152         // B smem stride (halves): 304B rows
#define A_SZ  (128*ASTR)  // halves
#define B_SZ  (GBK*BSTR)
#define STGH  (A_SZ + B_SZ)               // halves per stage
#define GEMM_SMEM (2*STGH*2)              // bytes

__device__ __forceinline__ void gemm_f16_mainloop(
    __half* smem,
    const __half* __restrict__ Ag, int lda,
    const __half* __restrict__ Bg, int ldb,
    float acc[2][8][4])
{
    int tid = threadIdx.x;
    int wid = tid >> 5, lane = tid & 31;
    int wm = (wid & 3) * 32, wn = (wid >> 2) * 64;

    uint32_t sb = smem_u32(smem);

    // staging indices (per thread)
    int arow = tid >> 1, aseg = (tid & 1) * 4;     // A: 128 rows x 8 segs; 4 segs/thread
    int brow = tid >> 2, bseg = (tid & 3) * 4;     // B: 64 rows x 16 segs; 4 segs/thread

    // ldmatrix bases (within a stage; add stage offset per use)
    uint32_t abase = (uint32_t)((wm + (lane & 7) + ((lane >> 3) & 1) * 8) * ASTR
                                + ((lane >> 4) & 1) * 8) * 2;
    uint32_t bbase = (uint32_t)(A_SZ + ((lane & 7) + ((lane >> 3) & 1) * 8) * BSTR
                                + wn + ((lane >> 4) & 1) * 8) * 2;

    #pragma unroll
    for (int mt = 0; mt < 2; mt++)
        #pragma unroll
        for (int nt = 0; nt < 8; nt++)
            #pragma unroll
            for (int q = 0; q < 4; q++) acc[mt][nt][q] = 0.f;

    // prologue: stage chunk 0 into stage 0
    {
        const __half* As = Ag + (size_t)arow * lda + aseg * 8;
        uint32_t ad = sb + (uint32_t)(arow * ASTR + aseg * 8) * 2;
        #pragma unroll
        for (int s = 0; s < 4; s++) CP16(ad + s*16, As + s*8);
        const __half* Bsrc = Bg + (size_t)brow * ldb + bseg * 8;
        uint32_t bd = sb + (uint32_t)(A_SZ + brow * BSTR + bseg * 8) * 2;
        #pragma unroll
        for (int s = 0; s < 4; s++) CP16(bd + s*16, Bsrc + s*8);
        CP_COMMIT();
    }

    for (int c = 0; c < GCH; c++) {
        __syncthreads();   // readers of the buffer we are about to fill are done
        if (c + 1 < GCH) {
            int k0 = (c + 1) * GBK;
            uint32_t stoff = (uint32_t)(((c + 1) & 1) * STGH) * 2;
            const __half* As = Ag + (size_t)arow * lda + k0 + aseg * 8;
            uint32_t ad = sb + stoff + (uint32_t)(arow * ASTR + aseg * 8) * 2;
            #pragma unroll
            for (int s = 0; s < 4; s++) CP16(ad + s*16, As + s*8);
            const __half* Bsrc = Bg + (size_t)(k0 + brow) * ldb + bseg * 8;
            uint32_t bd = sb + stoff + (uint32_t)(A_SZ + brow * BSTR + bseg * 8) * 2;
            #pragma unroll
            for (int s = 0; s < 4; s++) CP16(bd + s*16, Bsrc + s*8);
            CP_COMMIT();
            CP_WAIT1();
        } else {
            CP_WAIT0();
        }
        __syncthreads();   // chunk c visible to all

        uint32_t stoff = (uint32_t)((c & 1) * STGH) * 2;
        uint32_t ab = sb + stoff + abase;
        uint32_t bbs = sb + stoff + bbase;

        #pragma unroll
        for (int ks = 0; ks < 4; ks++) {
            uint32_t af[2][4];
            #pragma unroll
            for (int mt = 0; mt < 2; mt++)
                ldsm4(af[mt][0], af[mt][1], af[mt][2], af[mt][3],
                      ab + (uint32_t)(mt * 16 * ASTR + ks * 16) * 2);
            #pragma unroll
            for (int nb = 0; nb < 4; nb++) {
                uint32_t t0, t1, t2, t3;
                ldsm4t(t0, t1, t2, t3,
                       bbs + (uint32_t)(ks * 16 * BSTR + nb * 16) * 2);
                uint32_t lo[2] = {t0, t1}, hi[2] = {t2, t3};
                #pragma unroll
                for (int mt = 0; mt < 2; mt++) {
                    mma_f16(acc[mt][nb * 2],     af[mt], lo);
                    mma_f16(acc[mt][nb * 2 + 1], af[mt], hi);
                }
            }
        }
    }
}

// ===========================================================================
// QKV projection: hz 0..27 q, 28..31 k, 32..35 v
// ===========================================================================
__global__ __launch_bounds__(256, 2) void qkv_mma_kernel(
    float* __restrict__ outk, float* __restrict__ outv)
{
    extern __shared__ __align__(16) __half smem_g[];
    int m0 = blockIdx.x * 128;
    int hz = blockIdx.y;

    float acc[2][8][4];
    gemm_f16_mainloop(smem_g, g_xh + (size_t)m0 * DM, DM,
                      g_wh + (size_t)hz * DM * HH, HH, acc);

    int tid = threadIdx.x;
    int wid = tid >> 5, lane = tid & 31;
    int wm = (wid & 3) * 32, wn = (wid >> 2) * 64;
    int g = lane >> 2, tg = lane & 3;

    #pragma unroll
    for (int mt = 0; mt < 2; mt++) {
        #pragma unroll
        for (int h2 = 0; h2 < 2; h2++) {
            int row = wm + mt * 16 + g + h2 * 8;
            int mg = m0 + row;
            int b = mg / TT, t = mg - b * TT;
            float* dst;
            size_t voff = 0;
            if (hz < NQ)
                dst = g_q + ((size_t)mg * NQ + hz) * HH;
            else if (hz < 32)
                dst = outk + (((size_t)(b * SEQ + SCACHE + t)) * NKV + (hz - NQ)) * HH;
            else {
                voff = (((size_t)(b * SEQ + SCACHE + t)) * NKV + (hz - 32)) * HH;
                dst = outv + voff;
            }
            #pragma unroll
            for (int nt = 0; nt < 8; nt++) {
                float2 v = make_float2(acc[mt][nt][h2 * 2], acc[mt][nt][h2 * 2 + 1]);
                int col = wn + nt * 8 + tg * 2;
                *(float2*)(dst + col) = v;
                if (hz >= 32)
                    *(uint32_t*)&g_vh[voff + col] = pack_h2(v.x, v.y);
            }
        }
    }
}

// ===========================================================================
// Output projection: out = g_ench @ woh
// ===========================================================================
__global__ __launch_bounds__(256, 2) void out_mma_kernel(float* __restrict__ out)
{
    extern __shared__ __align__(16) __half smem_g[];
    int m0 = blockIdx.x * 128;
    int n0 = blockIdx.y * 128;

    float acc[2][8][4];
    gemm_f16_mainloop(smem_g, g_ench + (size_t)m0 * DM, DM, g_woh + n0, DM, acc);

    int tid = threadIdx.x;
    int wid = tid >> 5, lane = tid & 31;
    int wm = (wid & 3) * 32, wn = (wid >> 2) * 64;
    int g = lane >> 2, tg = lane & 3;

    #pragma unroll
    for (int mt = 0; mt < 2; mt++) {
        #pragma unroll
        for (int h2 = 0; h2 < 2; h2++) {
            int row = wm + mt * 16 + g + h2 * 8;
            float* dst = out + (size_t)(m0 + row) * DM + n0;
            #pragma unroll
            for (int nt = 0; nt < 8; nt++) {
                float2 v = make_float2(acc[mt][nt][h2 * 2], acc[mt][nt][h2 * 2 + 1]);
                *(float2*)(dst + wn + nt * 8 + tg * 2) = v;
            }
        }
    }
}

// ---------------------------------------------------------------------------
// mRoPE: q fp32 -> g_qh fp16 (scaled); k in outk fp32 in place + g_kh fp16
// ---------------------------------------------------------------------------
__global__ void rope_kernel(const int* __restrict__ positions,
                            float* __restrict__ outk)
{
    int idx = blockIdx.x*blockDim.x + threadIdx.x;
    if (idx >= BB*TT*64) return;
    int i = idx & 63;
    int t = (idx >> 6) & (TT-1);
    int b = idx >> 15;

    int j = (i < 16) ? 0 : ((i < 40) ? 1 : 2);
    int pos = positions[(j*BB + b)*TT + t];

    double inv = exp2(((double)(-2*i) / 128.0) * 19.931568569324174);
    double ang = (double)pos * inv;
    double sd, cd;
    sincos(ang, &sd, &cd);
    float c = (float)cd, s = (float)sd;
    const float qs = 0.08838834764831845f;

    size_t qbase = ((size_t)(b*TT + t))*NQ*HH;
    #pragma unroll 4
    for (int n = 0; n < NQ; n++) {
        float x1 = g_q[qbase + n*HH + i];
        float x2 = g_q[qbase + n*HH + i + 64];
        g_qh[qbase + n*HH + i]      = __float2half_rn((x1*c - x2*s)*qs);
        g_qh[qbase + n*HH + i + 64] = __float2half_rn((x2*c + x1*s)*qs);
    }
    size_t kbase = ((size_t)(b*SEQ + SCACHE + t))*NKV*HH;
    #pragma unroll
    for (int kh = 0; kh < NKV; kh++) {
        float x1 = outk[kbase + kh*HH + i];
        float x2 = outk[kbase + kh*HH + i + 64];
        float y1 = x1*c - x2*s;
        float y2 = x2*c + x1*s;
        outk[kbase + kh*HH + i]      = y1;
        outk[kbase + kh*HH + i + 64] = y2;
        g_kh[kbase + kh*HH + i]      = __float2half_rn(y1);
        g_kh[kbase + kh*HH + i + 64] = __float2half_rn(y2);
    }
}

// ===========================================================================
// Flash attention: fp16 + ldmatrix + cp.async double-buffered K/V.
// CTA: 64 queries x 1 head x 1 batch; 4 warps, warp owns 16 rows.
// ===========================================================================
#define KSH 136                       // smem stride halves (272B rows)
#define AST (2*64*KSH)                // halves per stage (K + V)
#define ATTN_SMEM (2*AST*2)           // bytes

__global__ __launch_bounds__(128, 3) void attn_f16_kernel()
{
    extern __shared__ __align__(16) __half smem_a[];
    uint32_t sb = smem_u32(smem_a);

    int t0 = blockIdx.x * 64;
    int n  = blockIdx.y;
    int b  = blockIdx.z;
    int kh = n / GRP;
    int tid = threadIdx.x, wid = tid >> 5, lane = tid & 31;
    int g = lane >> 2, tg = lane & 3;
    int wm = wid * 16;
    int r0 = wm + g, r1 = r0 + 8;

    // staging indices: 8 K-segs + 8 V-segs per thread per chunk
    int srow = tid >> 4, sseg = (tid & 15);      // 128 threads: rows 0..7 base
    // each thread covers rows srow, srow+8, ... srow+56 for its seg

    // ldmatrix lane bases (within stage)
    uint32_t kfrag = (uint32_t)(((lane & 7) + ((lane >> 4) & 1) * 8) * KSH
                                + ((lane >> 3) & 1) * 8) * 2;
    uint32_t vfrag = (uint32_t)(64*KSH*2) +
                     (uint32_t)(((lane & 7) + ((lane >> 3) & 1) * 8) * KSH
                                + ((lane >> 4) & 1) * 8) * 2;

    // Q fragments from g_qh
    uint32_t qa[8][4];
    {
        const __half* q0 = g_qh + (((size_t)(b*TT + t0 + r0))*NQ + n)*HH;
        const __half* q1 = g_qh + (((size_t)(b*TT + t0 + r1))*NQ + n)*HH;
        #pragma unroll
        for (int ks = 0; ks < 8; ks++) {
            qa[ks][0] = *(const uint32_t*)(q0 + ks*16 + 2*tg);
            qa[ks][1] = *(const uint32_t*)(q1 + ks*16 + 2*tg);
            qa[ks][2] = *(const uint32_t*)(q0 + ks*16 + 2*tg + 8);
            qa[ks][3] = *(const uint32_t*)(q1 + ks*16 + 2*tg + 8);
        }
    }

    float oacc[16][4];
    #pragma unroll
    for (int nt = 0; nt < 16; nt++)
        #pragma unroll
        for (int q = 0; q < 4; q++) oacc[nt][q] = 0.f;
    float mrow[2] = {-FLT_MAX, -FLT_MAX};
    float lrow[2] = {0.f, 0.f};

    int nchunks = (SCACHE + t0 + 64) >> 6;
    const __half* kbase_g = &g_kh[(((size_t)b*SEQ)*NKV + kh)*HH];
    const __half* vbase_g = &g_vh[(((size_t)b*SEQ)*NKV + kh)*HH];

    // prologue: stage chunk 0 into stage 0
    {
        uint32_t kd = sb + (uint32_t)(srow * KSH + sseg * 8) * 2;
        uint32_t vd = kd + (uint32_t)(64*KSH) * 2;
        #pragma unroll
        for (int rr = 0; rr < 8; rr++) {
            size_t soff = (size_t)(srow + rr*8) * (NKV*HH) + sseg * 8;
            CP16(kd + (uint32_t)(rr*8*KSH)*2, kbase_g + soff);
            CP16(vd + (uint32_t)(rr*8*KSH)*2, vbase_g + soff);
        }
        CP_COMMIT();
    }

    for (int ch = 0; ch < nchunks; ch++) {
        __syncthreads();   // readers of the buffer about to be filled are done
        if (ch + 1 < nchunks) {
            int s1 = (ch + 1) * 64;
            uint32_t stoff = (uint32_t)(((ch + 1) & 1) * AST) * 2;
            uint32_t kd = sb + stoff + (uint32_t)(srow * KSH + sseg * 8) * 2;
            uint32_t vd = kd + (uint32_t)(64*KSH) * 2;
            #pragma unroll
            for (int rr = 0; rr < 8; rr++) {
                size_t soff = (size_t)(s1 + srow + rr*8) * (NKV*HH) + sseg * 8;
                CP16(kd + (uint32_t)(rr*8*KSH)*2, kbase_g + soff);
                CP16(vd + (uint32_t)(rr*8*KSH)*2, vbase_g + soff);
            }
            CP_COMMIT();
            CP_WAIT1();
        } else {
            CP_WAIT0();
        }
        __syncthreads();   // chunk ch visible

        uint32_t stoff = (uint32_t)((ch & 1) * AST) * 2;
        uint32_t kaddr = sb + stoff + kfrag;
        uint32_t vaddr = sb + stoff + vfrag;

        // ---- S = Q K^T ----
        float sacc[8][4];
        #pragma unroll
        for (int nt = 0; nt < 8; nt++)
            #pragma unroll
            for (int q = 0; q < 4; q++) sacc[nt][q] = 0.f;

        #pragma unroll
        for (int ks = 0; ks < 8; ks++) {
            #pragma unroll
            for (int kb = 0; kb < 4; kb++) {
                uint32_t b0, b1, b2, b3;
                ldsm4(b0, b1, b2, b3, kaddr + (uint32_t)(kb*16*KSH + ks*16)*2);
                uint32_t lo[2] = {b0, b1}, hi[2] = {b2, b3};
                mma_f16(sacc[2*kb],   qa[ks], lo);
                mma_f16(sacc[2*kb+1], qa[ks], hi);
            }
        }

        // ---- causal mask (final chunk only) ----
        if (ch == nchunks - 1) {
            int s0 = ch * 64;
            int smax0 = SCACHE + t0 + r0;
            int smax1 = SCACHE + t0 + r1;
            #pragma unroll
            for (int nt = 0; nt < 8; nt++) {
                int col = s0 + nt*8 + 2*tg;
                if (col     > smax0) sacc[nt][0] = -FLT_MAX;
                if (col + 1 > smax0) sacc[nt][1] = -FLT_MAX;
                if (col     > smax1) sacc[nt][2] = -FLT_MAX;
                if (col + 1 > smax1) sacc[nt][3] = -FLT_MAX;
            }
        }

        // ---- online softmax; P packed into PV A-fragments ----
        uint32_t pfrag[4][4];
        #pragma unroll
        for (int hr = 0; hr < 2; hr++) {
            float mx = -FLT_MAX;
            #pragma unroll
            for (int nt = 0; nt < 8; nt++)
                mx = fmaxf(mx, fmaxf(sacc[nt][hr*2], sacc[nt][hr*2+1]));
            mx = fmaxf(mx, __shfl_xor_sync(0xffffffffu, mx, 1));
            mx = fmaxf(mx, __shfl_xor_sync(0xffffffffu, mx, 2));
            float mnew = fmaxf(mrow[hr], mx);
            float corr = __expf(mrow[hr] - mnew);
            mrow[hr] = mnew;
            float rs = 0.f;
            #pragma unroll
            for (int nt = 0; nt < 8; nt++) {
                float p0 = __expf(sacc[nt][hr*2]   - mnew);
                float p1 = __expf(sacc[nt][hr*2+1] - mnew);
                rs += p0 + p1;
                pfrag[nt >> 1][(nt & 1) * 2 + hr] = pack_h2(p0, p1);
            }
            rs += __shfl_xor_sync(0xffffffffu, rs, 1);
            rs += __shfl_xor_sync(0xffffffffu, rs, 2);
            lrow[hr] = lrow[hr]*corr + rs;
            #pragma unroll
            for (int nt = 0; nt < 16; nt++) {
                oacc[nt][hr*2]   *= corr;
                oacc[nt][hr*2+1] *= corr;
            }
        }

        // ---- O += P V ----
        #pragma unroll
        for (int kk = 0; kk < 4; kk++) {
            #pragma unroll
            for (int nb = 0; nb < 8; nb++) {
                uint32_t t0v, t1v, t2v, t3v;
                ldsm4t(t0v, t1v, t2v, t3v,
                       vaddr + (uint32_t)(kk*16*KSH + nb*16)*2);
                uint32_t lo[2] = {t0v, t1v}, hi[2] = {t2v, t3v};
                mma_f16(oacc[2*nb],   pfrag[kk], lo);
                mma_f16(oacc[2*nb+1], pfrag[kk], hi);
            }
        }
    }

    // ---- finalize: write enc fp16 ----
    float inv0 = 1.f / lrow[0];
    float inv1 = 1.f / lrow[1];
    __half* e0 = g_ench + (((size_t)(b*TT + t0 + r0))*NQ + n)*HH;
    __half* e1 = g_ench + (((size_t)(b*TT + t0 + r1))*NQ + n)*HH;
    #pragma unroll
    for (int nt = 0; nt < 16; nt++) {
        int col = nt*8 + 2*tg;
        *(uint32_t*)(e0 + col) = pack_h2(oacc[nt][0]*inv0, oacc[nt][1]*inv0);
        *(uint32_t*)(e1 + col) = pack_h2(oacc[nt][2]*inv1, oacc[nt][3]*inv1);
    }
}

// ---------------------------------------------------------------------------
// Launch
// ---------------------------------------------------------------------------
extern "C" void kernel_launch(void* const* d_in, const int* in_sizes, int n_in,
                              void* d_out, int out_size)
{
    const float* x         = (const float*)d_in[0];
    const int*   positions = (const int*)d_in[1];
    const float* cache_k   = (const float*)d_in[3];
    const float* cache_v   = (const float*)d_in[4];
    const float* wq        = (const float*)d_in[5];
    const float* wk        = (const float*)d_in[6];
    const float* wv        = (const float*)d_in[7];
    const float* wo        = (const float*)d_in[8];

    float* out  = (float*)d_out;
    float* outk = out + (size_t)OUT_ELEMS;
    float* outv = outk + (size_t)KV_ELEMS;

    __half *xh_p, *wh_p, *woh_p, *kh_p, *vh_p;
    cudaGetSymbolAddress((void**)&xh_p, g_xh);
    cudaGetSymbolAddress((void**)&wh_p, g_wh);
    cudaGetSymbolAddress((void**)&woh_p, g_woh);
    cudaGetSymbolAddress((void**)&kh_p, g_kh);
    cudaGetSymbolAddress((void**)&vh_p, g_vh);

    cudaFuncSetAttribute(qkv_mma_kernel, cudaFuncAttributeMaxDynamicSharedMemorySize, GEMM_SMEM);
    cudaFuncSetAttribute(out_mma_kernel, cudaFuncAttributeMaxDynamicSharedMemorySize, GEMM_SMEM);
    cudaFuncSetAttribute(attn_f16_kernel, cudaFuncAttributeMaxDynamicSharedMemorySize, ATTN_SMEM);

    // fp32 -> fp16 conversions
    conv_kernel<<<1024, 256>>>((const float4*)x, (uint2*)xh_p, BB*TT*DM/4);
    conv_kernel<<<2048, 256>>>((const float4*)wq, (uint2*)wh_p, NQ*DM*HH/4);
    conv_kernel<<<512, 256>>>((const float4*)wk, (uint2*)(wh_p + (size_t)NQ*DM*HH), NKV*DM*HH/4);
    conv_kernel<<<512, 256>>>((const float4*)wv, (uint2*)(wh_p + (size_t)32*DM*HH), NKV*DM*HH/4);
    conv_kernel<<<2048, 256>>>((const float4*)wo, (uint2*)woh_p, DM*DM/4);

    cache_copy_kernel<<<1024, 256>>>((const float4*)cache_k, (const float4*)cache_v,
                                     (float4*)outk, (float4*)outv,
                                     (uint2*)kh_p, (uint2*)vh_p);
    qkv_mma_kernel<<<dim3(8, 36), 256, GEMM_SMEM>>>(outk, outv);
    rope_kernel<<<(BB*TT*64 + 255)/256, 256>>>(positions, outk);
    attn_f16_kernel<<<dim3(TT/64, NQ, BB), 128, ATTN_SMEM>>>();
    out_mma_kernel<<<dim3(8, 28), 256, GEMM_SMEM>>>(out);
}

// round 14
// speedup vs baseline: 1.1552x; 1.1552x over previous
#include <cuda_runtime.h>
#include <cuda_fp16.h>
#include <math.h>
#include <float.h>
#include <stdint.h>

// Problem constants
#define BB 2
#define TT 512
#define DM 3584
#define NQ 28
#define NKV 4
#define GRP 7
#define HH 128
#define SCACHE 3584
#define SEQ 4096

#define OUT_ELEMS (BB*TT*DM)
#define KV_ELEMS  (BB*SEQ*NKV*HH)

// Scratch
__device__ float  g_q  [BB*TT*NQ*HH];     // q proj fp32 (pre-rope)
__device__ __half g_qh [BB*TT*NQ*HH];     // q roped+scaled fp16
__device__ __half g_kh [KV_ELEMS];        // k cache fp16 (roped)
__device__ __half g_vh [KV_ELEMS];        // v cache fp16
__device__ float  g_enc[BB*TT*NQ*HH];     // attention output fp32

__device__ __forceinline__ void mma_f16(float c[4], const uint32_t a[4], const uint32_t b[2]) {
    asm volatile("mma.sync.aligned.m16n8k16.row.col.f32.f16.f16.f32 "
        "{%0,%1,%2,%3}, {%4,%5,%6,%7}, {%8,%9}, {%0,%1,%2,%3};"
        : "+f"(c[0]), "+f"(c[1]), "+f"(c[2]), "+f"(c[3])
        : "r"(a[0]), "r"(a[1]), "r"(a[2]), "r"(a[3]), "r"(b[0]), "r"(b[1]));
}
__device__ __forceinline__ void ldsm4(uint32_t& r0, uint32_t& r1, uint32_t& r2, uint32_t& r3,
                                      uint32_t addr) {
    asm volatile("ldmatrix.sync.aligned.m8n8.x4.shared.b16 {%0,%1,%2,%3}, [%4];"
        : "=r"(r0), "=r"(r1), "=r"(r2), "=r"(r3) : "r"(addr));
}
__device__ __forceinline__ void ldsm4t(uint32_t& r0, uint32_t& r1, uint32_t& r2, uint32_t& r3,
                                       uint32_t addr) {
    asm volatile("ldmatrix.sync.aligned.m8n8.x4.trans.shared.b16 {%0,%1,%2,%3}, [%4];"
        : "=r"(r0), "=r"(r1), "=r"(r2), "=r"(r3) : "r"(addr));
}
__device__ __forceinline__ uint32_t smem_u32(const void* p) {
    uint32_t a;
    asm("{ .reg .u64 t; cvta.to.shared.u64 t, %1; cvt.u32.u64 %0, t; }" : "=r"(a) : "l"(p));
    return a;
}
__device__ __forceinline__ uint32_t pack_h2(float a, float b) {
    __half2 h = __floats2half2_rn(a, b);
    return *(uint32_t*)&h;
}
#define CP16(dst, src) \
    asm volatile("cp.async.cg.shared.global [%0], [%1], 16;" :: "r"(dst), "l"(src))
#define CP_COMMIT() asm volatile("cp.async.commit_group;" ::: "memory")
#define CP_WAIT1()  asm volatile("cp.async.wait_group 1;" ::: "memory")
#define CP_WAIT0()  asm volatile("cp.async.wait_group 0;" ::: "memory")

// ---------------------------------------------------------------------------
// Cache copy: fp32 outputs + fp16 mirrors (rows < SCACHE)
// ---------------------------------------------------------------------------
__global__ void cache_copy_kernel(const float4* __restrict__ ck,
                                  const float4* __restrict__ cv,
                                  float4* __restrict__ outk,
                                  float4* __restrict__ outv,
                                  uint2* __restrict__ kh,
                                  uint2* __restrict__ vh)
{
    const int per_b = SCACHE*NKV*HH/4;
    const int n4 = BB * per_b;
    for (int idx = blockIdx.x*blockDim.x + threadIdx.x; idx < n4;
         idx += gridDim.x*blockDim.x) {
        int b = idx / per_b;
        int r = idx - b*per_b;
        size_t o = (size_t)b*(SEQ*NKV*HH/4) + r;
        float4 a = ck[idx];
        float4 c = cv[idx];
        outk[o] = a;
        outv[o] = c;
        uint2 ka, vb;
        ka.x = pack_h2(a.x, a.y); ka.y = pack_h2(a.z, a.w);
        vb.x = pack_h2(c.x, c.y); vb.y = pack_h2(c.z, c.w);
        kh[o] = ka;
        vh[o] = vb;
    }
}

// ===========================================================================
// Dense GEMM — fp32 global operands, inline cvt to fp16 smem, ldmatrix(+trans)
// A row-major [128 x K] (lda); B row-major [K x 128] (ldb), staged [k][n].
// BK=32, register prefetch, 256 threads, 8 warps, warp tile 32x64.
// ===========================================================================
#define GBK  32
#define GCH  (DM/GBK)     // 112
#define ASTR 40           // A smem stride halves (80B rows)
#define BSTR 136          // B smem stride halves (272B rows)

__device__ __forceinline__ void gemm_f16_mainloop(
    const float* __restrict__ Ag, int lda,
    const float* __restrict__ Bg, int ldb,
    float acc[2][8][4])
{
    __shared__ __align__(16) __half As[128*ASTR];
    __shared__ __align__(16) __half Bs[GBK*BSTR];

    int tid = threadIdx.x;
    int wid = tid >> 5, lane = tid & 31;
    int wm = (wid & 3) * 32, wn = (wid >> 2) * 64;

    uint32_t as_b = smem_u32(As), bs_b = smem_u32(Bs);

    // staging indices
    int am = tid >> 1, akq = (tid & 1) * 4;      // A: 128 rows x 8 f4-slots; 4/thread
    int bk = tid >> 3, bn4 = (tid & 7) * 4;      // B: 32 rows x 32 f4-slots; 4/thread

    // ldmatrix lane bases (bytes)
    uint32_t abase = as_b + (uint32_t)((wm + (lane & 7) + ((lane >> 3) & 1) * 8) * ASTR
                                       + ((lane >> 4) & 1) * 8) * 2;
    uint32_t bbase = bs_b + (uint32_t)(((lane & 7) + ((lane >> 3) & 1) * 8) * BSTR
                                       + wn + ((lane >> 4) & 1) * 8) * 2;

    #pragma unroll
    for (int mt = 0; mt < 2; mt++)
        #pragma unroll
        for (int nt = 0; nt < 8; nt++)
            #pragma unroll
            for (int q = 0; q < 4; q++) acc[mt][nt][q] = 0.f;

    float4 ra[4], rb[4];

    // ---- load + store chunk 0 ----
    #pragma unroll
    for (int it = 0; it < 4; it++) {
        ra[it] = *(const float4*)(Ag + (size_t)am * lda + (akq + it) * 4);
        rb[it] = *(const float4*)(Bg + (size_t)(bk) * ldb + bn4 * 4 + it * 32 * ldb / 32 * 0 + 0);
    }
    // (B rows: bk covers 0..31 via tid>>3; each it loads a different k row group)
    #pragma unroll
    for (int it = 0; it < 4; it++)
        rb[it] = *(const float4*)(Bg + (size_t)(bk & 31) * ldb + bn4 * 4);
    // NOTE: the two loops above are replaced below by correct indexing
    {
        #pragma unroll
        for (int it = 0; it < 4; it++) {
            int idx = it * 256 + tid;
            int m = idx >> 3, kq = idx & 7;
            ra[it] = *(const float4*)(Ag + (size_t)m * lda + kq * 4);
            int kr = idx >> 5 & 31, n4 = idx & 31;
            rb[it] = *(const float4*)(Bg + (size_t)kr * ldb + n4 * 4);
        }
        #pragma unroll
        for (int it = 0; it < 4; it++) {
            int idx = it * 256 + tid;
            int m = idx >> 3, kq = idx & 7;
            uint2 av;
            av.x = pack_h2(ra[it].x, ra[it].y);
            av.y = pack_h2(ra[it].z, ra[it].w);
            *(uint2*)&As[m * ASTR + kq * 4] = av;
            int kr = idx >> 5 & 31, n4 = idx & 31;
            uint2 bv;
            bv.x = pack_h2(rb[it].x, rb[it].y);
            bv.y = pack_h2(rb[it].z, rb[it].w);
            *(uint2*)&Bs[kr * BSTR + n4 * 4] = bv;
        }
    }
    __syncthreads();

    for (int c = 0; c < GCH; c++) {
        // prefetch next chunk to registers
        if (c + 1 < GCH) {
            int k0 = (c + 1) * GBK;
            #pragma unroll
            for (int it = 0; it < 4; it++) {
                int idx = it * 256 + tid;
                int m = idx >> 3, kq = idx & 7;
                ra[it] = *(const float4*)(Ag + (size_t)m * lda + k0 + kq * 4);
                int kr = idx >> 5 & 31, n4 = idx & 31;
                rb[it] = *(const float4*)(Bg + (size_t)(k0 + kr) * ldb + n4 * 4);
            }
        }

        // compute: 2 ksteps of k16
        #pragma unroll
        for (int ks = 0; ks < 2; ks++) {
            uint32_t af[2][4];
            #pragma unroll
            for (int mt = 0; mt < 2; mt++)
                ldsm4(af[mt][0], af[mt][1], af[mt][2], af[mt][3],
                      abase + (uint32_t)(mt * 16 * ASTR + ks * 16) * 2);
            #pragma unroll
            for (int nb = 0; nb < 4; nb++) {
                uint32_t t0, t1, t2, t3;
                ldsm4t(t0, t1, t2, t3,
                       bbase + (uint32_t)(ks * 16 * BSTR + nb * 16) * 2);
                uint32_t lo[2] = {t0, t1}, hi[2] = {t2, t3};
                #pragma unroll
                for (int mt = 0; mt < 2; mt++) {
                    mma_f16(acc[mt][nb * 2],     af[mt], lo);
                    mma_f16(acc[mt][nb * 2 + 1], af[mt], hi);
                }
            }
        }
        __syncthreads();

        if (c + 1 < GCH) {
            #pragma unroll
            for (int it = 0; it < 4; it++) {
                int idx = it * 256 + tid;
                int m = idx >> 3, kq = idx & 7;
                uint2 av;
                av.x = pack_h2(ra[it].x, ra[it].y);
                av.y = pack_h2(ra[it].z, ra[it].w);
                *(uint2*)&As[m * ASTR + kq * 4] = av;
                int kr = idx >> 5 & 31, n4 = idx & 31;
                uint2 bv;
                bv.x = pack_h2(rb[it].x, rb[it].y);
                bv.y = pack_h2(rb[it].z, rb[it].w);
                *(uint2*)&Bs[kr * BSTR + n4 * 4] = bv;
            }
            __syncthreads();
        }
    }
}

// ===========================================================================
// QKV projection: hz 0..27 q, 28..31 k, 32..35 v
// ===========================================================================
__global__ __launch_bounds__(256, 2) void qkv_mma_kernel(
    const float* __restrict__ x,
    const float* __restrict__ wq, const float* __restrict__ wk,
    const float* __restrict__ wv,
    float* __restrict__ outk, float* __restrict__ outv)
{
    int m0 = blockIdx.x * 128;
    int hz = blockIdx.y;
    const float* Bg;
    if (hz < NQ)          Bg = wq + (size_t)hz * DM * HH;
    else if (hz < 32)     Bg = wk + (size_t)(hz - NQ) * DM * HH;
    else                  Bg = wv + (size_t)(hz - 32) * DM * HH;

    float acc[2][8][4];
    gemm_f16_mainloop(x + (size_t)m0 * DM, DM, Bg, HH, acc);

    int tid = threadIdx.x;
    int wid = tid >> 5, lane = tid & 31;
    int wm = (wid & 3) * 32, wn = (wid >> 2) * 64;
    int g = lane >> 2, tg = lane & 3;

    #pragma unroll
    for (int mt = 0; mt < 2; mt++) {
        #pragma unroll
        for (int h2 = 0; h2 < 2; h2++) {
            int row = wm + mt * 16 + g + h2 * 8;
            int mg = m0 + row;
            int b = mg / TT, t = mg - b * TT;
            float* dst;
            size_t voff = 0;
            if (hz < NQ)
                dst = g_q + ((size_t)mg * NQ + hz) * HH;
            else if (hz < 32)
                dst = outk + (((size_t)(b * SEQ + SCACHE + t)) * NKV + (hz - NQ)) * HH;
            else {
                voff = (((size_t)(b * SEQ + SCACHE + t)) * NKV + (hz - 32)) * HH;
                dst = outv + voff;
            }
            #pragma unroll
            for (int nt = 0; nt < 8; nt++) {
                float2 v = make_float2(acc[mt][nt][h2 * 2], acc[mt][nt][h2 * 2 + 1]);
                int col = wn + nt * 8 + tg * 2;
                *(float2*)(dst + col) = v;
                if (hz >= 32)
                    *(uint32_t*)&g_vh[voff + col] = pack_h2(v.x, v.y);
            }
        }
    }
}

// ===========================================================================
// Output projection: out = g_enc @ wo
// ===========================================================================
__global__ __launch_bounds__(256, 2) void out_mma_kernel(
    const float* __restrict__ wo, float* __restrict__ out)
{
    int m0 = blockIdx.x * 128;
    int n0 = blockIdx.y * 128;

    float acc[2][8][4];
    gemm_f16_mainloop(g_enc + (size_t)m0 * DM, DM, wo + n0, DM, acc);

    int tid = threadIdx.x;
    int wid = tid >> 5, lane = tid & 31;
    int wm = (wid & 3) * 32, wn = (wid >> 2) * 64;
    int g = lane >> 2, tg = lane & 3;

    #pragma unroll
    for (int mt = 0; mt < 2; mt++) {
        #pragma unroll
        for (int h2 = 0; h2 < 2; h2++) {
            int row = wm + mt * 16 + g + h2 * 8;
            float* dst = out + (size_t)(m0 + row) * DM + n0;
            #pragma unroll
            for (int nt = 0; nt < 8; nt++) {
                float2 v = make_float2(acc[mt][nt][h2 * 2], acc[mt][nt][h2 * 2 + 1]);
                *(float2*)(dst + wn + nt * 8 + tg * 2) = v;
            }
        }
    }
}

// ---------------------------------------------------------------------------
// mRoPE: q fp32 -> g_qh fp16 (scaled); k fp32 in outk updated + g_kh fp16
// ---------------------------------------------------------------------------
__global__ void rope_kernel(const int* __restrict__ positions,
                            float* __restrict__ outk)
{
    int idx = blockIdx.x*blockDim.x + threadIdx.x;
    if (idx >= BB*TT*64) return;
    int i = idx & 63;
    int t = (idx >> 6) & (TT-1);
    int b = idx >> 15;

    int j = (i < 16) ? 0 : ((i < 40) ? 1 : 2);
    int pos = positions[(j*BB + b)*TT + t];

    double inv = exp2(((double)(-2*i) / 128.0) * 19.931568569324174);
    double ang = (double)pos * inv;
    double sd, cd;
    sincos(ang, &sd, &cd);
    float c = (float)cd, s = (float)sd;
    const float qs = 0.08838834764831845f;

    size_t qbase = ((size_t)(b*TT + t))*NQ*HH;
    #pragma unroll 4
    for (int n = 0; n < NQ; n++) {
        float x1 = g_q[qbase + n*HH + i];
        float x2 = g_q[qbase + n*HH + i + 64];
        g_qh[qbase + n*HH + i]      = __float2half_rn((x1*c - x2*s)*qs);
        g_qh[qbase + n*HH + i + 64] = __float2half_rn((x2*c + x1*s)*qs);
    }
    size_t kbase = ((size_t)(b*SEQ + SCACHE + t))*NKV*HH;
    #pragma unroll
    for (int kh = 0; kh < NKV; kh++) {
        float x1 = outk[kbase + kh*HH + i];
        float x2 = outk[kbase + kh*HH + i + 64];
        float y1 = x1*c - x2*s;
        float y2 = x2*c + x1*s;
        outk[kbase + kh*HH + i]      = y1;
        outk[kbase + kh*HH + i + 64] = y2;
        g_kh[kbase + kh*HH + i]      = __float2half_rn(y1);
        g_kh[kbase + kh*HH + i + 64] = __float2half_rn(y2);
    }
}

// ===========================================================================
// Flash attention: fp16 + ldmatrix + cp.async double-buffered K/V.
// CTA: 64 queries x 1 head x 1 batch; 4 warps, warp owns 16 rows.
// ===========================================================================
#define KSH 136                       // smem stride halves (272B rows)
#define AST (2*64*KSH)                // halves per stage (K + V)
#define ATTN_SMEM (2*AST*2)           // bytes

__global__ __launch_bounds__(128, 3) void attn_f16_kernel()
{
    extern __shared__ __align__(16) __half smem_a[];
    uint32_t sb = smem_u32(smem_a);

    int t0 = blockIdx.x * 64;
    int n  = blockIdx.y;
    int b  = blockIdx.z;
    int kh = n / GRP;
    int tid = threadIdx.x, wid = tid >> 5, lane = tid & 31;
    int g = lane >> 2, tg = lane & 3;
    int wm = wid * 16;
    int r0 = wm + g, r1 = r0 + 8;

    int srow = tid >> 4, sseg = (tid & 15);

    uint32_t kfrag = (uint32_t)(((lane & 7) + ((lane >> 4) & 1) * 8) * KSH
                                + ((lane >> 3) & 1) * 8) * 2;
    uint32_t vfrag = (uint32_t)(64*KSH*2) +
                     (uint32_t)(((lane & 7) + ((lane >> 3) & 1) * 8) * KSH
                                + ((lane >> 4) & 1) * 8) * 2;

    // Q fragments from g_qh
    uint32_t qa[8][4];
    {
        const __half* q0 = g_qh + (((size_t)(b*TT + t0 + r0))*NQ + n)*HH;
        const __half* q1 = g_qh + (((size_t)(b*TT + t0 + r1))*NQ + n)*HH;
        #pragma unroll
        for (int ks = 0; ks < 8; ks++) {
            qa[ks][0] = *(const uint32_t*)(q0 + ks*16 + 2*tg);
            qa[ks][1] = *(const uint32_t*)(q1 + ks*16 + 2*tg);
            qa[ks][2] = *(const uint32_t*)(q0 + ks*16 + 2*tg + 8);
            qa[ks][3] = *(const uint32_t*)(q1 + ks*16 + 2*tg + 8);
        }
    }

    float oacc[16][4];
    #pragma unroll
    for (int nt = 0; nt < 16; nt++)
        #pragma unroll
        for (int q = 0; q < 4; q++) oacc[nt][q] = 0.f;
    float mrow[2] = {-FLT_MAX, -FLT_MAX};
    float lrow[2] = {0.f, 0.f};

    int nchunks = (SCACHE + t0 + 64) >> 6;
    const __half* kbase_g = &g_kh[(((size_t)b*SEQ)*NKV + kh)*HH];
    const __half* vbase_g = &g_vh[(((size_t)b*SEQ)*NKV + kh)*HH];

    // prologue: stage chunk 0 into stage 0
    {
        uint32_t kd = sb + (uint32_t)(srow * KSH + sseg * 8) * 2;
        uint32_t vd = kd + (uint32_t)(64*KSH) * 2;
        #pragma unroll
        for (int rr = 0; rr < 8; rr++) {
            size_t soff = (size_t)(srow + rr*8) * (NKV*HH) + sseg * 8;
            CP16(kd + (uint32_t)(rr*8*KSH)*2, kbase_g + soff);
            CP16(vd + (uint32_t)(rr*8*KSH)*2, vbase_g + soff);
        }
        CP_COMMIT();
    }

    for (int ch = 0; ch < nchunks; ch++) {
        __syncthreads();
        if (ch + 1 < nchunks) {
            int s1 = (ch + 1) * 64;
            uint32_t stoff = (uint32_t)(((ch + 1) & 1) * AST) * 2;
            uint32_t kd = sb + stoff + (uint32_t)(srow * KSH + sseg * 8) * 2;
            uint32_t vd = kd + (uint32_t)(64*KSH) * 2;
            #pragma unroll
            for (int rr = 0; rr < 8; rr++) {
                size_t soff = (size_t)(s1 + srow + rr*8) * (NKV*HH) + sseg * 8;
                CP16(kd + (uint32_t)(rr*8*KSH)*2, kbase_g + soff);
                CP16(vd + (uint32_t)(rr*8*KSH)*2, vbase_g + soff);
            }
            CP_COMMIT();
            CP_WAIT1();
        } else {
            CP_WAIT0();
        }
        __syncthreads();

        uint32_t stoff = (uint32_t)((ch & 1) * AST) * 2;
        uint32_t kaddr = sb + stoff + kfrag;
        uint32_t vaddr = sb + stoff + vfrag;

        // ---- S = Q K^T ----
        float sacc[8][4];
        #pragma unroll
        for (int nt = 0; nt < 8; nt++)
            #pragma unroll
            for (int q = 0; q < 4; q++) sacc[nt][q] = 0.f;

        #pragma unroll
        for (int ks = 0; ks < 8; ks++) {
            #pragma unroll
            for (int kb = 0; kb < 4; kb++) {
                uint32_t b0, b1, b2, b3;
                ldsm4(b0, b1, b2, b3, kaddr + (uint32_t)(kb*16*KSH + ks*16)*2);
                uint32_t lo[2] = {b0, b1}, hi[2] = {b2, b3};
                mma_f16(sacc[2*kb],   qa[ks], lo);
                mma_f16(sacc[2*kb+1], qa[ks], hi);
            }
        }

        // ---- causal mask (final chunk only) ----
        if (ch == nchunks - 1) {
            int s0 = ch * 64;
            int smax0 = SCACHE + t0 + r0;
            int smax1 = SCACHE + t0 + r1;
            #pragma unroll
            for (int nt = 0; nt < 8; nt++) {
                int col = s0 + nt*8 + 2*tg;
                if (col     > smax0) sacc[nt][0] = -FLT_MAX;
                if (col + 1 > smax0) sacc[nt][1] = -FLT_MAX;
                if (col     > smax1) sacc[nt][2] = -FLT_MAX;
                if (col + 1 > smax1) sacc[nt][3] = -FLT_MAX;
            }
        }

        // ---- online softmax; P packed into PV A-fragments ----
        uint32_t pfrag[4][4];
        #pragma unroll
        for (int hr = 0; hr < 2; hr++) {
            float mx = -FLT_MAX;
            #pragma unroll
            for (int nt = 0; nt < 8; nt++)
                mx = fmaxf(mx, fmaxf(sacc[nt][hr*2], sacc[nt][hr*2+1]));
            mx = fmaxf(mx, __shfl_xor_sync(0xffffffffu, mx, 1));
            mx = fmaxf(mx, __shfl_xor_sync(0xffffffffu, mx, 2));
            float mnew = fmaxf(mrow[hr], mx);
            float corr = __expf(mrow[hr] - mnew);
            mrow[hr] = mnew;
            float rs = 0.f;
            #pragma unroll
            for (int nt = 0; nt < 8; nt++) {
                float p0 = __expf(sacc[nt][hr*2]   - mnew);
                float p1 = __expf(sacc[nt][hr*2+1] - mnew);
                rs += p0 + p1;
                pfrag[nt >> 1][(nt & 1) * 2 + hr] = pack_h2(p0, p1);
            }
            rs += __shfl_xor_sync(0xffffffffu, rs, 1);
            rs += __shfl_xor_sync(0xffffffffu, rs, 2);
            lrow[hr] = lrow[hr]*corr + rs;
            #pragma unroll
            for (int nt = 0; nt < 16; nt++) {
                oacc[nt][hr*2]   *= corr;
                oacc[nt][hr*2+1] *= corr;
            }
        }

        // ---- O += P V ----
        #pragma unroll
        for (int kk = 0; kk < 4; kk++) {
            #pragma unroll
            for (int nb = 0; nb < 8; nb++) {
                uint32_t t0v, t1v, t2v, t3v;
                ldsm4t(t0v, t1v, t2v, t3v,
                       vaddr + (uint32_t)(kk*16*KSH + nb*16)*2);
                uint32_t lo[2] = {t0v, t1v}, hi[2] = {t2v, t3v};
                mma_f16(oacc[2*nb],   pfrag[kk], lo);
                mma_f16(oacc[2*nb+1], pfrag[kk], hi);
            }
        }
    }

    // ---- finalize: write enc fp32 ----
    float inv0 = 1.f / lrow[0];
    float inv1 = 1.f / lrow[1];
    float* e0 = g_enc + (((size_t)(b*TT + t0 + r0))*NQ + n)*HH;
    float* e1 = g_enc + (((size_t)(b*TT + t0 + r1))*NQ + n)*HH;
    #pragma unroll
    for (int nt = 0; nt < 16; nt++) {
        int col = nt*8 + 2*tg;
        *(float2*)(e0 + col) = make_float2(oacc[nt][0]*inv0, oacc[nt][1]*inv0);
        *(float2*)(e1 + col) = make_float2(oacc[nt][2]*inv1, oacc[nt][3]*inv1);
    }
}

// ---------------------------------------------------------------------------
// Launch
// ---------------------------------------------------------------------------
extern "C" void kernel_launch(void* const* d_in, const int* in_sizes, int n_in,
                              void* d_out, int out_size)
{
    const float* x         = (const float*)d_in[0];
    const int*   positions = (const int*)d_in[1];
    const float* cache_k   = (const float*)d_in[3];
    const float* cache_v   = (const float*)d_in[4];
    const float* wq        = (const float*)d_in[5];
    const float* wk        = (const float*)d_in[6];
    const float* wv        = (const float*)d_in[7];
    const float* wo        = (const float*)d_in[8];

    float* out  = (float*)d_out;
    float* outk = out + (size_t)OUT_ELEMS;
    float* outv = outk + (size_t)KV_ELEMS;

    __half *kh_p, *vh_p;
    cudaGetSymbolAddress((void**)&kh_p, g_kh);
    cudaGetSymbolAddress((void**)&vh_p, g_vh);

    cudaFuncSetAttribute(attn_f16_kernel, cudaFuncAttributeMaxDynamicSharedMemorySize, ATTN_SMEM);

    cache_copy_kernel<<<1024, 256>>>((const float4*)cache_k, (const float4*)cache_v,
                                     (float4*)outk, (float4*)outv,
                                     (uint2*)kh_p, (uint2*)vh_p);
    qkv_mma_kernel<<<dim3(8, 36), 256>>>(x, wq, wk, wv, outk, outv);
    rope_kernel<<<(BB*TT*64 + 255)/256, 256>>>(positions, outk);
    attn_f16_kernel<<<dim3(TT/64, NQ, BB), 128, ATTN_SMEM>>>();
    out_mma_kernel<<<dim3(8, 28), 256>>>(wo, out);
}

// round 16
// speedup vs baseline: 1.1680x; 1.0111x over previous
#include <cuda_runtime.h>
#include <cuda_fp16.h>
#include <math.h>
#include <float.h>
#include <stdint.h>

// Problem constants
#define BB 2
#define TT 512
#define DM 3584
#define NQ 28
#define NKV 4
#define GRP 7
#define HH 128
#define SCACHE 3584
#define SEQ 4096

#define OUT_ELEMS (BB*TT*DM)
#define KV_ELEMS  (BB*SEQ*NKV*HH)
#define BTNQ  (BB*TT*NQ)              // 28672 rows
#define BTNQH (BTNQ*HH)               // 3,670,016

// Scratch
__device__ float  g_q  [BTNQH];       // q proj fp32 (pre-rope)
__device__ __half g_qh [BTNQH];       // q roped+scaled fp16
__device__ __half g_kh [KV_ELEMS];    // k cache fp16 (roped)
__device__ __half g_vh [KV_ELEMS];    // v cache fp16
__device__ float  g_enc[BTNQH];       // attention output fp32
__device__ float  g_po [2*BTNQH];     // split partial O (unnormalized)
__device__ float  g_pml[2*BTNQ*2];    // split partial (m, l)

__device__ __forceinline__ void mma_f16(float c[4], const uint32_t a[4], const uint32_t b[2]) {
    asm volatile("mma.sync.aligned.m16n8k16.row.col.f32.f16.f16.f32 "
        "{%0,%1,%2,%3}, {%4,%5,%6,%7}, {%8,%9}, {%0,%1,%2,%3};"
        : "+f"(c[0]), "+f"(c[1]), "+f"(c[2]), "+f"(c[3])
        : "r"(a[0]), "r"(a[1]), "r"(a[2]), "r"(a[3]), "r"(b[0]), "r"(b[1]));
}
__device__ __forceinline__ void ldsm4(uint32_t& r0, uint32_t& r1, uint32_t& r2, uint32_t& r3,
                                      uint32_t addr) {
    asm volatile("ldmatrix.sync.aligned.m8n8.x4.shared.b16 {%0,%1,%2,%3}, [%4];"
        : "=r"(r0), "=r"(r1), "=r"(r2), "=r"(r3) : "r"(addr));
}
__device__ __forceinline__ void ldsm4t(uint32_t& r0, uint32_t& r1, uint32_t& r2, uint32_t& r3,
                                       uint32_t addr) {
    asm volatile("ldmatrix.sync.aligned.m8n8.x4.trans.shared.b16 {%0,%1,%2,%3}, [%4];"
        : "=r"(r0), "=r"(r1), "=r"(r2), "=r"(r3) : "r"(addr));
}
__device__ __forceinline__ uint32_t smem_u32(const void* p) {
    uint32_t a;
    asm("{ .reg .u64 t; cvta.to.shared.u64 t, %1; cvt.u32.u64 %0, t; }" : "=r"(a) : "l"(p));
    return a;
}
__device__ __forceinline__ uint32_t pack_h2(float a, float b) {
    __half2 h = __floats2half2_rn(a, b);
    return *(uint32_t*)&h;
}
#define CP16(dst, src) \
    asm volatile("cp.async.cg.shared.global [%0], [%1], 16;" :: "r"(dst), "l"(src))
#define CP_COMMIT() asm volatile("cp.async.commit_group;" ::: "memory")
#define CP_WAIT1()  asm volatile("cp.async.wait_group 1;" ::: "memory")
#define CP_WAIT0()  asm volatile("cp.async.wait_group 0;" ::: "memory")

// ---------------------------------------------------------------------------
// Cache copy: fp32 outputs + fp16 mirrors (rows < SCACHE)
// ---------------------------------------------------------------------------
__global__ void cache_copy_kernel(const float4* __restrict__ ck,
                                  const float4* __restrict__ cv,
                                  float4* __restrict__ outk,
                                  float4* __restrict__ outv,
                                  uint2* __restrict__ kh,
                                  uint2* __restrict__ vh)
{
    const int per_b = SCACHE*NKV*HH/4;
    const int n4 = BB * per_b;
    for (int idx = blockIdx.x*blockDim.x + threadIdx.x; idx < n4;
         idx += gridDim.x*blockDim.x) {
        int b = idx / per_b;
        int r = idx - b*per_b;
        size_t o = (size_t)b*(SEQ*NKV*HH/4) + r;
        float4 a = ck[idx];
        float4 c = cv[idx];
        outk[o] = a;
        outv[o] = c;
        uint2 ka, vb;
        ka.x = pack_h2(a.x, a.y); ka.y = pack_h2(a.z, a.w);
        vb.x = pack_h2(c.x, c.y); vb.y = pack_h2(c.z, c.w);
        kh[o] = ka;
        vh[o] = vb;
    }
}

// ===========================================================================
// Dense GEMM — fp32 global operands, inline cvt to fp16 smem, ldmatrix(+trans)
// (unchanged from round 14)
// ===========================================================================
#define GBK  32
#define GCH  (DM/GBK)     // 112
#define ASTR 40           // A smem stride halves (80B rows)
#define BSTR 136          // B smem stride halves (272B rows)

__device__ __forceinline__ void gemm_f16_mainloop(
    const float* __restrict__ Ag, int lda,
    const float* __restrict__ Bg, int ldb,
    float acc[2][8][4])
{
    __shared__ __align__(16) __half As[128*ASTR];
    __shared__ __align__(16) __half Bs[GBK*BSTR];

    int tid = threadIdx.x;
    int wid = tid >> 5, lane = tid & 31;
    int wm = (wid & 3) * 32, wn = (wid >> 2) * 64;

    uint32_t as_b = smem_u32(As), bs_b = smem_u32(Bs);

    uint32_t abase = as_b + (uint32_t)((wm + (lane & 7) + ((lane >> 3) & 1) * 8) * ASTR
                                       + ((lane >> 4) & 1) * 8) * 2;
    uint32_t bbase = bs_b + (uint32_t)(((lane & 7) + ((lane >> 3) & 1) * 8) * BSTR
                                       + wn + ((lane >> 4) & 1) * 8) * 2;

    #pragma unroll
    for (int mt = 0; mt < 2; mt++)
        #pragma unroll
        for (int nt = 0; nt < 8; nt++)
            #pragma unroll
            for (int q = 0; q < 4; q++) acc[mt][nt][q] = 0.f;

    float4 ra[4], rb[4];

    #pragma unroll
    for (int it = 0; it < 4; it++) {
        int idx = it * 256 + tid;
        int m = idx >> 3, kq = idx & 7;
        ra[it] = *(const float4*)(Ag + (size_t)m * lda + kq * 4);
        int kr = idx >> 5 & 31, n4 = idx & 31;
        rb[it] = *(const float4*)(Bg + (size_t)kr * ldb + n4 * 4);
    }
    #pragma unroll
    for (int it = 0; it < 4; it++) {
        int idx = it * 256 + tid;
        int m = idx >> 3, kq = idx & 7;
        uint2 av;
        av.x = pack_h2(ra[it].x, ra[it].y);
        av.y = pack_h2(ra[it].z, ra[it].w);
        *(uint2*)&As[m * ASTR + kq * 4] = av;
        int kr = idx >> 5 & 31, n4 = idx & 31;
        uint2 bv;
        bv.x = pack_h2(rb[it].x, rb[it].y);
        bv.y = pack_h2(rb[it].z, rb[it].w);
        *(uint2*)&Bs[kr * BSTR + n4 * 4] = bv;
    }
    __syncthreads();

    for (int c = 0; c < GCH; c++) {
        if (c + 1 < GCH) {
            int k0 = (c + 1) * GBK;
            #pragma unroll
            for (int it = 0; it < 4; it++) {
                int idx = it * 256 + tid;
                int m = idx >> 3, kq = idx & 7;
                ra[it] = *(const float4*)(Ag + (size_t)m * lda + k0 + kq * 4);
                int kr = idx >> 5 & 31, n4 = idx & 31;
                rb[it] = *(const float4*)(Bg + (size_t)(k0 + kr) * ldb + n4 * 4);
            }
        }

        #pragma unroll
        for (int ks = 0; ks < 2; ks++) {
            uint32_t af[2][4];
            #pragma unroll
            for (int mt = 0; mt < 2; mt++)
                ldsm4(af[mt][0], af[mt][1], af[mt][2], af[mt][3],
                      abase + (uint32_t)(mt * 16 * ASTR + ks * 16) * 2);
            #pragma unroll
            for (int nb = 0; nb < 4; nb++) {
                uint32_t t0, t1, t2, t3;
                ldsm4t(t0, t1, t2, t3,
                       bbase + (uint32_t)(ks * 16 * BSTR + nb * 16) * 2);
                uint32_t lo[2] = {t0, t1}, hi[2] = {t2, t3};
                #pragma unroll
                for (int mt = 0; mt < 2; mt++) {
                    mma_f16(acc[mt][nb * 2],     af[mt], lo);
                    mma_f16(acc[mt][nb * 2 + 1], af[mt], hi);
                }
            }
        }
        __syncthreads();

        if (c + 1 < GCH) {
            #pragma unroll
            for (int it = 0; it < 4; it++) {
                int idx = it * 256 + tid;
                int m = idx >> 3, kq = idx & 7;
                uint2 av;
                av.x = pack_h2(ra[it].x, ra[it].y);
                av.y = pack_h2(ra[it].z, ra[it].w);
                *(uint2*)&As[m * ASTR + kq * 4] = av;
                int kr = idx >> 5 & 31, n4 = idx & 31;
                uint2 bv;
                bv.x = pack_h2(rb[it].x, rb[it].y);
                bv.y = pack_h2(rb[it].z, rb[it].w);
                *(uint2*)&Bs[kr * BSTR + n4 * 4] = bv;
            }
            __syncthreads();
        }
    }
}

// ===========================================================================
// QKV projection: hz 0..27 q, 28..31 k, 32..35 v
// ===========================================================================
__global__ __launch_bounds__(256, 2) void qkv_mma_kernel(
    const float* __restrict__ x,
    const float* __restrict__ wq, const float* __restrict__ wk,
    const float* __restrict__ wv,
    float* __restrict__ outk, float* __restrict__ outv)
{
    int m0 = blockIdx.x * 128;
    int hz = blockIdx.y;
    const float* Bg;
    if (hz < NQ)          Bg = wq + (size_t)hz * DM * HH;
    else if (hz < 32)     Bg = wk + (size_t)(hz - NQ) * DM * HH;
    else                  Bg = wv + (size_t)(hz - 32) * DM * HH;

    float acc[2][8][4];
    gemm_f16_mainloop(x + (size_t)m0 * DM, DM, Bg, HH, acc);

    int tid = threadIdx.x;
    int wid = tid >> 5, lane = tid & 31;
    int wm = (wid & 3) * 32, wn = (wid >> 2) * 64;
    int g = lane >> 2, tg = lane & 3;

    #pragma unroll
    for (int mt = 0; mt < 2; mt++) {
        #pragma unroll
        for (int h2 = 0; h2 < 2; h2++) {
            int row = wm + mt * 16 + g + h2 * 8;
            int mg = m0 + row;
            int b = mg / TT, t = mg - b * TT;
            float* dst;
            size_t voff = 0;
            if (hz < NQ)
                dst = g_q + ((size_t)mg * NQ + hz) * HH;
            else if (hz < 32)
                dst = outk + (((size_t)(b * SEQ + SCACHE + t)) * NKV + (hz - NQ)) * HH;
            else {
                voff = (((size_t)(b * SEQ + SCACHE + t)) * NKV + (hz - 32)) * HH;
                dst = outv + voff;
            }
            #pragma unroll
            for (int nt = 0; nt < 8; nt++) {
                float2 v = make_float2(acc[mt][nt][h2 * 2], acc[mt][nt][h2 * 2 + 1]);
                int col = wn + nt * 8 + tg * 2;
                *(float2*)(dst + col) = v;
                if (hz >= 32)
                    *(uint32_t*)&g_vh[voff + col] = pack_h2(v.x, v.y);
            }
        }
    }
}

// ===========================================================================
// Output projection: out = g_enc @ wo
// ===========================================================================
__global__ __launch_bounds__(256, 2) void out_mma_kernel(
    const float* __restrict__ wo, float* __restrict__ out)
{
    int m0 = blockIdx.x * 128;
    int n0 = blockIdx.y * 128;

    float acc[2][8][4];
    gemm_f16_mainloop(g_enc + (size_t)m0 * DM, DM, wo + n0, DM, acc);

    int tid = threadIdx.x;
    int wid = tid >> 5, lane = tid & 31;
    int wm = (wid & 3) * 32, wn = (wid >> 2) * 64;
    int g = lane >> 2, tg = lane & 3;

    #pragma unroll
    for (int mt = 0; mt < 2; mt++) {
        #pragma unroll
        for (int h2 = 0; h2 < 2; h2++) {
            int row = wm + mt * 16 + g + h2 * 8;
            float* dst = out + (size_t)(m0 + row) * DM + n0;
            #pragma unroll
            for (int nt = 0; nt < 8; nt++) {
                float2 v = make_float2(acc[mt][nt][h2 * 2], acc[mt][nt][h2 * 2 + 1]);
                *(float2*)(dst + wn + nt * 8 + tg * 2) = v;
            }
        }
    }
}

// ---------------------------------------------------------------------------
// mRoPE: q fp32 -> g_qh fp16 (scaled); k fp32 in outk updated + g_kh fp16
// ---------------------------------------------------------------------------
__global__ void rope_kernel(const int* __restrict__ positions,
                            float* __restrict__ outk)
{
    int idx = blockIdx.x*blockDim.x + threadIdx.x;
    if (idx >= BB*TT*64) return;
    int i = idx & 63;
    int t = (idx >> 6) & (TT-1);
    int b = idx >> 15;

    int j = (i < 16) ? 0 : ((i < 40) ? 1 : 2);
    int pos = positions[(j*BB + b)*TT + t];

    double inv = exp2(((double)(-2*i) / 128.0) * 19.931568569324174);
    double ang = (double)pos * inv;
    double sd, cd;
    sincos(ang, &sd, &cd);
    float c = (float)cd, s = (float)sd;
    const float qs = 0.08838834764831845f;

    size_t qbase = ((size_t)(b*TT + t))*NQ*HH;
    #pragma unroll 4
    for (int n = 0; n < NQ; n++) {
        float x1 = g_q[qbase + n*HH + i];
        float x2 = g_q[qbase + n*HH + i + 64];
        g_qh[qbase + n*HH + i]      = __float2half_rn((x1*c - x2*s)*qs);
        g_qh[qbase + n*HH + i + 64] = __float2half_rn((x2*c + x1*s)*qs);
    }
    size_t kbase = ((size_t)(b*SEQ + SCACHE + t))*NKV*HH;
    #pragma unroll
    for (int kh = 0; kh < NKV; kh++) {
        float x1 = outk[kbase + kh*HH + i];
        float x2 = outk[kbase + kh*HH + i + 64];
        float y1 = x1*c - x2*s;
        float y2 = x2*c + x1*s;
        outk[kbase + kh*HH + i]      = y1;
        outk[kbase + kh*HH + i + 64] = y2;
        g_kh[kbase + kh*HH + i]      = __float2half_rn(y1);
        g_kh[kbase + kh*HH + i + 64] = __float2half_rn(y2);
    }
}

// ===========================================================================
// Flash attention (split-S = 2): each CTA handles half the key chunks of a
// (64-query, head, batch) tile and emits unnormalized partial O + (m, l).
// grid (TT/64, NQ, BB*2); z = b*2 + s.
// ===========================================================================
#define KSH 136                       // smem stride halves (272B rows)
#define AST (2*64*KSH)                // halves per stage (K + V)
#define ATTN_SMEM (2*AST*2)           // bytes

__global__ __launch_bounds__(128, 3) void attn_f16_kernel()
{
    extern __shared__ __align__(16) __half smem_a[];
    uint32_t sb = smem_u32(smem_a);

    int t0 = blockIdx.x * 64;
    int n  = blockIdx.y;
    int bz = blockIdx.z;
    int b  = bz >> 1, sp = bz & 1;
    int kh = n / GRP;
    int tid = threadIdx.x, wid = tid >> 5, lane = tid & 31;
    int g = lane >> 2, tg = lane & 3;
    int wm = wid * 16;
    int r0 = wm + g, r1 = r0 + 8;

    int srow = tid >> 4, sseg = (tid & 15);

    uint32_t kfrag = (uint32_t)(((lane & 7) + ((lane >> 4) & 1) * 8) * KSH
                                + ((lane >> 3) & 1) * 8) * 2;
    uint32_t vfrag = (uint32_t)(64*KSH*2) +
                     (uint32_t)(((lane & 7) + ((lane >> 3) & 1) * 8) * KSH
                                + ((lane >> 4) & 1) * 8) * 2;

    // split chunk range
    int N = (SCACHE + t0 + 64) >> 6;
    int h = (N + 1) >> 1;
    int c0   = sp ? h : 0;
    int cEnd = sp ? N : h;
    int cnt  = cEnd - c0;

    // Q fragments from g_qh
    uint32_t qa[8][4];
    {
        const __half* q0 = g_qh + (((size_t)(b*TT + t0 + r0))*NQ + n)*HH;
        const __half* q1 = g_qh + (((size_t)(b*TT + t0 + r1))*NQ + n)*HH;
        #pragma unroll
        for (int ks = 0; ks < 8; ks++) {
            qa[ks][0] = *(const uint32_t*)(q0 + ks*16 + 2*tg);
            qa[ks][1] = *(const uint32_t*)(q1 + ks*16 + 2*tg);
            qa[ks][2] = *(const uint32_t*)(q0 + ks*16 + 2*tg + 8);
            qa[ks][3] = *(const uint32_t*)(q1 + ks*16 + 2*tg + 8);
        }
    }

    float oacc[16][4];
    #pragma unroll
    for (int nt = 0; nt < 16; nt++)
        #pragma unroll
        for (int q = 0; q < 4; q++) oacc[nt][q] = 0.f;
    float mrow[2] = {-FLT_MAX, -FLT_MAX};
    float lrow[2] = {0.f, 0.f};

    const __half* kbase_g = &g_kh[(((size_t)b*SEQ)*NKV + kh)*HH];
    const __half* vbase_g = &g_vh[(((size_t)b*SEQ)*NKV + kh)*HH];

    // prologue: stage local chunk 0 into stage 0
    {
        int sg = c0 * 64;
        uint32_t kd = sb + (uint32_t)(srow * KSH + sseg * 8) * 2;
        uint32_t vd = kd + (uint32_t)(64*KSH) * 2;
        #pragma unroll
        for (int rr = 0; rr < 8; rr++) {
            size_t soff = (size_t)(sg + srow + rr*8) * (NKV*HH) + sseg * 8;
            CP16(kd + (uint32_t)(rr*8*KSH)*2, kbase_g + soff);
            CP16(vd + (uint32_t)(rr*8*KSH)*2, vbase_g + soff);
        }
        CP_COMMIT();
    }

    for (int j = 0; j < cnt; j++) {
        int ch = c0 + j;
        __syncthreads();
        if (j + 1 < cnt) {
            int s1 = (ch + 1) * 64;
            uint32_t stoff = (uint32_t)(((j + 1) & 1) * AST) * 2;
            uint32_t kd = sb + stoff + (uint32_t)(srow * KSH + sseg * 8) * 2;
            uint32_t vd = kd + (uint32_t)(64*KSH) * 2;
            #pragma unroll
            for (int rr = 0; rr < 8; rr++) {
                size_t soff = (size_t)(s1 + srow + rr*8) * (NKV*HH) + sseg * 8;
                CP16(kd + (uint32_t)(rr*8*KSH)*2, kbase_g + soff);
                CP16(vd + (uint32_t)(rr*8*KSH)*2, vbase_g + soff);
            }
            CP_COMMIT();
            CP_WAIT1();
        } else {
            CP_WAIT0();
        }
        __syncthreads();

        uint32_t stoff = (uint32_t)((j & 1) * AST) * 2;
        uint32_t kaddr = sb + stoff + kfrag;
        uint32_t vaddr = sb + stoff + vfrag;

        // ---- S = Q K^T ----
        float sacc[8][4];
        #pragma unroll
        for (int nt = 0; nt < 8; nt++)
            #pragma unroll
            for (int q = 0; q < 4; q++) sacc[nt][q] = 0.f;

        #pragma unroll
        for (int ks = 0; ks < 8; ks++) {
            #pragma unroll
            for (int kb = 0; kb < 4; kb++) {
                uint32_t b0, b1, b2, b3;
                ldsm4(b0, b1, b2, b3, kaddr + (uint32_t)(kb*16*KSH + ks*16)*2);
                uint32_t lo[2] = {b0, b1}, hi[2] = {b2, b3};
                mma_f16(sacc[2*kb],   qa[ks], lo);
                mma_f16(sacc[2*kb+1], qa[ks], hi);
            }
        }

        // ---- causal mask (only the global final chunk, owned by split 1) ----
        if (ch == N - 1) {
            int s0 = ch * 64;
            int smax0 = SCACHE + t0 + r0;
            int smax1 = SCACHE + t0 + r1;
            #pragma unroll
            for (int nt = 0; nt < 8; nt++) {
                int col = s0 + nt*8 + 2*tg;
                if (col     > smax0) sacc[nt][0] = -FLT_MAX;
                if (col + 1 > smax0) sacc[nt][1] = -FLT_MAX;
                if (col     > smax1) sacc[nt][2] = -FLT_MAX;
                if (col + 1 > smax1) sacc[nt][3] = -FLT_MAX;
            }
        }

        // ---- online softmax; P packed into PV A-fragments ----
        uint32_t pfrag[4][4];
        #pragma unroll
        for (int hr = 0; hr < 2; hr++) {
            float mx = -FLT_MAX;
            #pragma unroll
            for (int nt = 0; nt < 8; nt++)
                mx = fmaxf(mx, fmaxf(sacc[nt][hr*2], sacc[nt][hr*2+1]));
            mx = fmaxf(mx, __shfl_xor_sync(0xffffffffu, mx, 1));
            mx = fmaxf(mx, __shfl_xor_sync(0xffffffffu, mx, 2));
            float mnew = fmaxf(mrow[hr], mx);
            float corr = __expf(mrow[hr] - mnew);
            mrow[hr] = mnew;
            float rs = 0.f;
            #pragma unroll
            for (int nt = 0; nt < 8; nt++) {
                float p0 = __expf(sacc[nt][hr*2]   - mnew);
                float p1 = __expf(sacc[nt][hr*2+1] - mnew);
                rs += p0 + p1;
                pfrag[nt >> 1][(nt & 1) * 2 + hr] = pack_h2(p0, p1);
            }
            rs += __shfl_xor_sync(0xffffffffu, rs, 1);
            rs += __shfl_xor_sync(0xffffffffu, rs, 2);
            lrow[hr] = lrow[hr]*corr + rs;
            #pragma unroll
            for (int nt = 0; nt < 16; nt++) {
                oacc[nt][hr*2]   *= corr;
                oacc[nt][hr*2+1] *= corr;
            }
        }

        // ---- O += P V ----
        #pragma unroll
        for (int kk = 0; kk < 4; kk++) {
            #pragma unroll
            for (int nb = 0; nb < 8; nb++) {
                uint32_t t0v, t1v, t2v, t3v;
                ldsm4t(t0v, t1v, t2v, t3v,
                       vaddr + (uint32_t)(kk*16*KSH + nb*16)*2);
                uint32_t lo[2] = {t0v, t1v}, hi[2] = {t2v, t3v};
                mma_f16(oacc[2*nb],   pfrag[kk], lo);
                mma_f16(oacc[2*nb+1], pfrag[kk], hi);
            }
        }
    }

    // ---- finalize: write unnormalized partial O and (m, l) ----
    size_t row0 = ((size_t)(b*TT + t0 + r0))*NQ + n;
    size_t row1 = ((size_t)(b*TT + t0 + r1))*NQ + n;
    float* o0 = g_po + (size_t)sp*BTNQH + row0*HH;
    float* o1 = g_po + (size_t)sp*BTNQH + row1*HH;
    #pragma unroll
    for (int nt = 0; nt < 16; nt++) {
        int col = nt*8 + 2*tg;
        *(float2*)(o0 + col) = make_float2(oacc[nt][0], oacc[nt][1]);
        *(float2*)(o1 + col) = make_float2(oacc[nt][2], oacc[nt][3]);
    }
    if (tg == 0) {
        float* pml = g_pml + (size_t)sp*BTNQ*2;
        pml[row0*2]     = mrow[0];
        pml[row0*2 + 1] = lrow[0];
        pml[row1*2]     = mrow[1];
        pml[row1*2 + 1] = lrow[1];
    }
}

// ---------------------------------------------------------------------------
// Combine split partials: exact online-softmax merge -> g_enc fp32
// ---------------------------------------------------------------------------
__global__ void attn_combine_kernel()
{
    const int tot = BTNQ * 32;    // float4 groups per partial
    const float4* po0 = (const float4*)g_po;
    const float4* po1 = (const float4*)(g_po + (size_t)BTNQH);
    float4* enc = (float4*)g_enc;
    for (int idx = blockIdx.x*blockDim.x + threadIdx.x; idx < tot;
         idx += gridDim.x*blockDim.x) {
        int r = idx >> 5;
        float m0 = g_pml[r*2],             l0 = g_pml[r*2 + 1];
        float m1 = g_pml[BTNQ*2 + r*2],    l1 = g_pml[BTNQ*2 + r*2 + 1];
        float m = fmaxf(m0, m1);
        float a0 = __expf(m0 - m), a1 = __expf(m1 - m);
        float inv = 1.f / (l0*a0 + l1*a1);
        float4 v0 = po0[idx];
        float4 v1 = po1[idx];
        float4 o;
        o.x = (v0.x*a0 + v1.x*a1) * inv;
        o.y = (v0.y*a0 + v1.y*a1) * inv;
        o.z = (v0.z*a0 + v1.z*a1) * inv;
        o.w = (v0.w*a0 + v1.w*a1) * inv;
        enc[idx] = o;
    }
}

// ---------------------------------------------------------------------------
// Launch
// ---------------------------------------------------------------------------
extern "C" void kernel_launch(void* const* d_in, const int* in_sizes, int n_in,
                              void* d_out, int out_size)
{
    const float* x         = (const float*)d_in[0];
    const int*   positions = (const int*)d_in[1];
    const float* cache_k   = (const float*)d_in[3];
    const float* cache_v   = (const float*)d_in[4];
    const float* wq        = (const float*)d_in[5];
    const float* wk        = (const float*)d_in[6];
    const float* wv        = (const float*)d_in[7];
    const float* wo        = (const float*)d_in[8];

    float* out  = (float*)d_out;
    float* outk = out + (size_t)OUT_ELEMS;
    float* outv = outk + (size_t)KV_ELEMS;

    __half *kh_p, *vh_p;
    cudaGetSymbolAddress((void**)&kh_p, g_kh);
    cudaGetSymbolAddress((void**)&vh_p, g_vh);

    cudaFuncSetAttribute(attn_f16_kernel, cudaFuncAttributeMaxDynamicSharedMemorySize, ATTN_SMEM);

    cache_copy_kernel<<<1024, 256>>>((const float4*)cache_k, (const float4*)cache_v,
                                     (float4*)outk, (float4*)outv,
                                     (uint2*)kh_p, (uint2*)vh_p);
    qkv_mma_kernel<<<dim3(8, 36), 256>>>(x, wq, wk, wv, outk, outv);
    rope_kernel<<<(BB*TT*64 + 255)/256, 256>>>(positions, outk);
    attn_f16_kernel<<<dim3(TT/64, NQ, BB*2), 128, ATTN_SMEM>>>();
    attn_combine_kernel<<<1024, 256>>>();
    out_mma_kernel<<<dim3(8, 28), 256>>>(wo, out);
}